// round 1
// baseline (speedup 1.0000x reference)
#include <cuda_runtime.h>
#include <cuda_bf16.h>
#include <math.h>

// Problem constants (fixed by the dataset)
#define N_ROWS 16384
#define DHALF  256
#define KDIM   512      // 2*D
#define VCODES 8192

// Tiling for the fused GEMM-argmin
#define BR 128          // rows per CTA
#define BC 128          // codes per tile
#define KC 32           // K chunk in smem
#define NTHREADS 256    // 16x16 threads, 8x8 micro-tile

// Scratch (no allocations allowed)
__device__ float g_w2[VCODES];
__device__ int   g_counts[VCODES];
__device__ int   g_idx[N_ROWS];

// ---------------------------------------------------------------------------
// Kernel 0: w2[v] = sum_k weight[v][k]^2   (one warp per code row)
// ---------------------------------------------------------------------------
__global__ void w2_kernel(const float* __restrict__ w) {
    int v = blockIdx.x * 8 + (threadIdx.x >> 5);
    int lane = threadIdx.x & 31;
    if (v >= VCODES) return;
    const float* wr = w + (size_t)v * KDIM;
    float s = 0.f;
#pragma unroll
    for (int p = 0; p < KDIM / 32; p++) {
        float x = wr[lane + p * 32];
        s = fmaf(x, x, s);
    }
#pragma unroll
    for (int m = 16; m >= 1; m >>= 1) s += __shfl_xor_sync(0xffffffffu, s, m);
    if (lane == 0) g_w2[v] = s;
}

// ---------------------------------------------------------------------------
// Kernel Z: zero the histogram
// ---------------------------------------------------------------------------
__global__ void zero_counts_kernel() {
    int i = blockIdx.x * blockDim.x + threadIdx.x;
    if (i < VCODES) g_counts[i] = 0;
}

// ---------------------------------------------------------------------------
// Kernel A: fused fp32 GEMM + argmin
//   score(n, v) = w2[v] - 2 * dot(z_flat[n], w[v])   (x2 row-constant dropped)
//   g_idx[n] = argmin_v score
// ---------------------------------------------------------------------------
__global__ __launch_bounds__(NTHREADS, 1)
void argmin_kernel(const float* __restrict__ zr, const float* __restrict__ zi,
                   const float* __restrict__ w) {
    __shared__ float As[KC][BR + 4];   // z tile, k-major (row stride 132 -> 16B aligned)
    __shared__ float Bs[KC][BC + 4];   // w tile, k-major

    const int t  = threadIdx.x;
    const int tx = t & 15;             // code direction
    const int ty = t >> 4;             // row direction
    const int r0 = blockIdx.x * BR;

    float best[8];
    int   bidx[8];
#pragma unroll
    for (int i = 0; i < 8; i++) { best[i] = 3.4e38f; bidx[i] = 0; }

    for (int ct = 0; ct < VCODES / BC; ct++) {
        const int c0 = ct * BC;
        float acc[8][8];
#pragma unroll
        for (int i = 0; i < 8; i++)
#pragma unroll
            for (int j = 0; j < 8; j++) acc[i][j] = 0.f;

        for (int kt = 0; kt < KDIM / KC; kt++) {
            // ---- load Z tile (BR x KC) into As[k][row], float4 global reads ----
            const float* zbase = (kt < (DHALF / KC)) ? zr : zi;
            const int kcol0 = kt * KC - ((kt < (DHALF / KC)) ? 0 : DHALF);
#pragma unroll
            for (int p = 0; p < 4; p++) {
                int e = t + p * NTHREADS;          // 0..1023 (float4 index)
                int rr = e >> 3, kk4 = e & 7;
                float4 v = *(const float4*)&zbase[(size_t)(r0 + rr) * DHALF + kcol0 + kk4 * 4];
                As[kk4 * 4 + 0][rr] = v.x;
                As[kk4 * 4 + 1][rr] = v.y;
                As[kk4 * 4 + 2][rr] = v.z;
                As[kk4 * 4 + 3][rr] = v.w;
            }
            // ---- load W tile (BC x KC) into Bs[k][code] ----
#pragma unroll
            for (int p = 0; p < 4; p++) {
                int e = t + p * NTHREADS;
                int rr = e >> 3, kk4 = e & 7;
                float4 v = *(const float4*)&w[(size_t)(c0 + rr) * KDIM + kt * KC + kk4 * 4];
                Bs[kk4 * 4 + 0][rr] = v.x;
                Bs[kk4 * 4 + 1][rr] = v.y;
                Bs[kk4 * 4 + 2][rr] = v.z;
                Bs[kk4 * 4 + 3][rr] = v.w;
            }
            __syncthreads();

            // ---- 8x8 register micro-tile FMA over this K chunk ----
#pragma unroll
            for (int k = 0; k < KC; k++) {
                float a[8], b[8];
                *(float4*)&a[0] = *(const float4*)&As[k][ty * 8];
                *(float4*)&a[4] = *(const float4*)&As[k][ty * 8 + 4];
                *(float4*)&b[0] = *(const float4*)&Bs[k][tx * 8];
                *(float4*)&b[4] = *(const float4*)&Bs[k][tx * 8 + 4];
#pragma unroll
                for (int i = 0; i < 8; i++)
#pragma unroll
                    for (int j = 0; j < 8; j++)
                        acc[i][j] = fmaf(a[i], b[j], acc[i][j]);
            }
            __syncthreads();
        }

        // ---- fold this code tile into the running argmin ----
        float w2t[8];
#pragma unroll
        for (int j = 0; j < 8; j++) w2t[j] = __ldg(&g_w2[c0 + tx * 8 + j]);
#pragma unroll
        for (int i = 0; i < 8; i++) {
#pragma unroll
            for (int j = 0; j < 8; j++) {
                float s = fmaf(-2.f, acc[i][j], w2t[j]);
                if (s < best[i]) { best[i] = s; bidx[i] = c0 + tx * 8 + j; }
            }
        }
    }

    // ---- reduce argmin across the 16 tx-lanes sharing each row ----
    // warp layout: lanes 0..15 have ty = 2w, lanes 16..31 have ty = 2w+1;
    // xor masks 8,4,2,1 stay inside each 16-lane half.
#pragma unroll
    for (int i = 0; i < 8; i++) {
        float v = best[i];
        int   bi = bidx[i];
#pragma unroll
        for (int m = 8; m >= 1; m >>= 1) {
            float ov = __shfl_xor_sync(0xffffffffu, v, m);
            int   oi = __shfl_xor_sync(0xffffffffu, bi, m);
            if (ov < v || (ov == v && oi < bi)) { v = ov; bi = oi; }
        }
        if (tx == 0) g_idx[r0 + ty * 8 + i] = bi;
    }
}

// ---------------------------------------------------------------------------
// Kernel B: gather z_q = weight[idx], write outputs, per-row loss, histogram
//   out layout: [z_q_real (N*D)] [z_q_imag (N*D)] [loss (N)] [idx (N)] [entropy (1)]
// ---------------------------------------------------------------------------
__global__ void gather_kernel(const float* __restrict__ zr, const float* __restrict__ zi,
                              const float* __restrict__ w, float* __restrict__ out) {
    int row  = blockIdx.x * 8 + (threadIdx.x >> 5);
    int lane = threadIdx.x & 31;
    if (row >= N_ROWS) return;

    int ci = g_idx[row];
    const float* wrow = w + (size_t)ci * KDIM;
    float ss = 0.f;
#pragma unroll
    for (int p = 0; p < DHALF / 32; p++) {
        int d = lane + p * 32;
        float wv = wrow[d];
        float zv = zr[(size_t)row * DHALF + d];
        out[(size_t)row * DHALF + d] = wv;
        float df = wv - zv;
        ss = fmaf(df, df, ss);
    }
#pragma unroll
    for (int p = 0; p < DHALF / 32; p++) {
        int d = lane + p * 32;
        float wv = wrow[DHALF + d];
        float zv = zi[(size_t)row * DHALF + d];
        out[(size_t)N_ROWS * DHALF + (size_t)row * DHALF + d] = wv;
        float df = wv - zv;
        ss = fmaf(df, df, ss);
    }
#pragma unroll
    for (int m = 16; m >= 1; m >>= 1) ss += __shfl_xor_sync(0xffffffffu, ss, m);
    if (lane == 0) {
        size_t base = (size_t)2 * N_ROWS * DHALF;
        out[base + row] = ss * (1.25f / (float)KDIM);      // codebook + 0.25*commitment
        out[base + N_ROWS + row] = (float)ci;              // index as float
        atomicAdd(&g_counts[ci], 1);
    }
}

// ---------------------------------------------------------------------------
// Kernel C: entropy of empirical code usage
// ---------------------------------------------------------------------------
__global__ void entropy_kernel(float* __restrict__ out) {
    __shared__ float red[1024];
    int t = threadIdx.x;
    float s = 0.f;
    for (int v = t; v < VCODES; v += 1024) {
        float p = (float)g_counts[v] * (1.f / (float)N_ROWS);
        s += p * logf(p + 1e-10f);   // p==0 contributes exactly 0
    }
    red[t] = s;
    __syncthreads();
    for (int m = 512; m >= 1; m >>= 1) {
        if (t < m) red[t] += red[t + m];
        __syncthreads();
    }
    if (t == 0) out[(size_t)2 * N_ROWS * DHALF + 2 * N_ROWS] = -red[0];
}

// ---------------------------------------------------------------------------
extern "C" void kernel_launch(void* const* d_in, const int* in_sizes, int n_in,
                              void* d_out, int out_size) {
    const float* zr = (const float*)d_in[0];
    const float* zi = (const float*)d_in[1];
    const float* w  = (const float*)d_in[2];
    float* out = (float*)d_out;

    w2_kernel<<<VCODES / 8, 256>>>(w);
    zero_counts_kernel<<<(VCODES + 1023) / 1024, 1024>>>();
    argmin_kernel<<<N_ROWS / BR, NTHREADS>>>(zr, zi, w);
    gather_kernel<<<N_ROWS / 8, 256>>>(zr, zi, w, out);
    entropy_kernel<<<1, 1024>>>(out);
}

// round 3
// speedup vs baseline: 1.2698x; 1.2698x over previous
#include <cuda_runtime.h>
#include <cstdint>
#include <math.h>

// Problem constants
#define N_ROWS 16384
#define DHALF  256
#define KDIM   512
#define VCODES 8192

// GEMM-argmin tiling
#define BR 128
#define BC 128
#define KC 32
#define N_TILES  (VCODES / BC)       // 64
#define K_CHUNKS (KDIM / KC)         // 16
#define TOTAL_IT (N_TILES * K_CHUNKS)// 1024
#define NTHREADS 256

// SMEM stage layout (floats): A[128][40], B[32][136], hi+lo each, double buffered
#define A_STRIDE 40
#define B_STRIDE 136
#define A_BYTES (128 * A_STRIDE * 4)         // 20480
#define B_BYTES (KC * B_STRIDE * 4)          // 17408
#define OFF_AH 0
#define OFF_AL (A_BYTES)
#define OFF_BH (2 * A_BYTES)
#define OFF_BL (2 * A_BYTES + B_BYTES)
#define STAGE_BYTES (2 * A_BYTES + 2 * B_BYTES)  // 75776
#define SM_RED (2 * STAGE_BYTES)                  // 151552
#define SMEM_TOTAL (SM_RED + 4096)                // 155648

// Scratch globals (no allocations allowed)
__device__ float g_w2[VCODES];
__device__ int   g_counts[VCODES];
__device__ int   g_idx[N_ROWS];
// z hi/lo: [row][512], k permuted within each 8-block: k%8 -> 2*(k%4) + (k%8)/4
__device__ float g_z_hi[(size_t)N_ROWS * KDIM];
__device__ float g_z_lo[(size_t)N_ROWS * KDIM];
// w hi/lo: [tile(64)][k(512)][col(128) permuted: p = (n%128)/8 + 16*(n%8)]
__device__ float g_w_hi[(size_t)VCODES * KDIM];
__device__ float g_w_lo[(size_t)VCODES * KDIM];

// ---------------------------------------------------------------------------
__device__ __forceinline__ uint32_t smem_u32(const void* p) {
    uint32_t a;
    asm("{ .reg .u64 t; cvta.to.shared.u64 t, %1; cvt.u32.u64 %0, t; }" : "=r"(a) : "l"(p));
    return a;
}
#define CP_ASYNC16(dst, src) \
    asm volatile("cp.async.cg.shared.global [%0], [%1], 16;" :: "r"(dst), "l"(src) : "memory")
#define CP_ASYNC_COMMIT() asm volatile("cp.async.commit_group;" ::: "memory")
#define CP_ASYNC_WAIT0()  asm volatile("cp.async.wait_group 0;" ::: "memory")
#define CP_ASYNC_WAIT1()  asm volatile("cp.async.wait_group 1;" ::: "memory")

#define MMA_TF32(C, a0, a1, a2, a3, b0, b1) \
    asm volatile("mma.sync.aligned.m16n8k8.row.col.f32.tf32.tf32.f32 " \
        "{%0,%1,%2,%3}, {%4,%5,%6,%7}, {%8,%9}, {%0,%1,%2,%3};" \
        : "+f"((C)[0]), "+f"((C)[1]), "+f"((C)[2]), "+f"((C)[3]) \
        : "r"(a0), "r"(a1), "r"(a2), "r"(a3), "r"(b0), "r"(b1))

__device__ __forceinline__ float to_tf32(float x) {
    uint32_t r;
    asm("cvt.rna.tf32.f32 %0, %1;" : "=r"(r) : "f"(x));
    return __uint_as_float(r);
}
__device__ __forceinline__ uint32_t fb(float x) { return __float_as_uint(x); }

// ---------------------------------------------------------------------------
// Split + permute z: hi/lo, k permuted within 8-blocks
// ---------------------------------------------------------------------------
__global__ void split_z_kernel(const float* __restrict__ zr, const float* __restrict__ zi) {
    int q = blockIdx.x * blockDim.x + threadIdx.x;
    if (q >= N_ROWS * KDIM) return;
    int row = q >> 9, k = q & 511;
    float v = (k < DHALF) ? zr[(size_t)row * DHALF + k] : zi[(size_t)row * DHALF + k - DHALF];
    float h = to_tf32(v), l = to_tf32(v - h);
    int kp = (k & ~7) | ((k & 3) << 1) | ((k >> 2) & 1);
    g_z_hi[(size_t)row * KDIM + kp] = h;
    g_z_lo[(size_t)row * KDIM + kp] = l;
}

// ---------------------------------------------------------------------------
// Split + transpose + permute w into [tile][k][pcol] layout
// block = (ct, kt): 128 codes x 32 k
// ---------------------------------------------------------------------------
__global__ void split_w_kernel(const float* __restrict__ w) {
    __shared__ float tile[128][33];
    int ct = blockIdx.x, kt = blockIdx.y;
    int t = threadIdx.x;
#pragma unroll
    for (int p = 0; p < 4; p++) {
        int e = t + p * 256;
        int r = e >> 3, g = e & 7;
        float4 v = *(const float4*)&w[(size_t)(ct * 128 + r) * KDIM + kt * 32 + g * 4];
        tile[r][g * 4 + 0] = v.x; tile[r][g * 4 + 1] = v.y;
        tile[r][g * 4 + 2] = v.z; tile[r][g * 4 + 3] = v.w;
    }
    __syncthreads();
#pragma unroll
    for (int p = 0; p < 16; p++) {
        int e = t + p * 256;
        int k = e >> 7, pc = e & 127;
        int n = (pc & 15) * 8 + (pc >> 4);            // invperm
        float v = tile[n][k];
        float h = to_tf32(v), l = to_tf32(v - h);
        size_t d = (size_t)ct * (KDIM * 128) + (size_t)(kt * 32 + k) * 128 + pc;
        g_w_hi[d] = h; g_w_lo[d] = l;
    }
}

// ---------------------------------------------------------------------------
__global__ void w2_kernel(const float* __restrict__ w) {
    int v = blockIdx.x * 8 + (threadIdx.x >> 5);
    int lane = threadIdx.x & 31;
    if (v >= VCODES) return;
    const float* wr = w + (size_t)v * KDIM;
    float s = 0.f;
#pragma unroll
    for (int p = 0; p < KDIM / 32; p++) { float x = wr[lane + p * 32]; s = fmaf(x, x, s); }
#pragma unroll
    for (int m = 16; m >= 1; m >>= 1) s += __shfl_xor_sync(0xffffffffu, s, m);
    if (lane == 0) g_w2[v] = s;
}

__global__ void zero_counts_kernel() {
    int i = blockIdx.x * blockDim.x + threadIdx.x;
    if (i < VCODES) g_counts[i] = 0;
}

// ---------------------------------------------------------------------------
// Stage loader: A 128x32 (hi+lo) + B 32x128 (hi+lo) via cp.async
// ---------------------------------------------------------------------------
__device__ __forceinline__ void load_stage(uint32_t st, int it, int r0, int t) {
    const int ct = it >> 4, kc = it & 15;
    const int k0 = kc * KC;
#pragma unroll
    for (int p = 0; p < 4; p++) {
        int e = t + p * NTHREADS;
        int row = e >> 3, g = e & 7;
        uint32_t doff = (uint32_t)(row * (A_STRIDE * 4) + g * 16);
        size_t s = (size_t)(r0 + row) * KDIM + k0 + g * 4;
        CP_ASYNC16(st + OFF_AH + doff, &g_z_hi[s]);
        CP_ASYNC16(st + OFF_AL + doff, &g_z_lo[s]);
    }
#pragma unroll
    for (int p = 0; p < 4; p++) {
        int e = t + p * NTHREADS;
        int kr = e >> 5, c = e & 31;
        uint32_t doff = (uint32_t)(kr * (B_STRIDE * 4) + c * 16);
        size_t s = (size_t)ct * (KDIM * 128) + (size_t)(k0 + kr) * 128 + c * 4;
        CP_ASYNC16(st + OFF_BH + doff, &g_w_hi[s]);
        CP_ASYNC16(st + OFF_BL + doff, &g_w_lo[s]);
    }
}

// ---------------------------------------------------------------------------
// Fused 3xTF32 mma.sync GEMM + argmin
// ---------------------------------------------------------------------------
__global__ __launch_bounds__(NTHREADS, 1)
void argmin_mma_kernel() {
    extern __shared__ char smem[];
    const int t = threadIdx.x;
    const int wid = t >> 5, lane = t & 31;
    const int warp_m = wid & 3, warp_n = wid >> 2;
    const int q = lane >> 2, c4 = lane & 3;
    const int r0 = blockIdx.x * BR;

    float acc[2][8][4];
#pragma unroll
    for (int mt = 0; mt < 2; mt++)
#pragma unroll
        for (int nt = 0; nt < 8; nt++)
#pragma unroll
            for (int j = 0; j < 4; j++) acc[mt][nt][j] = 0.f;

    float best[2][2] = {{3.4e38f, 3.4e38f}, {3.4e38f, 3.4e38f}};
    int   bidx[2][2] = {{0, 0}, {0, 0}};

    const uint32_t sb = smem_u32(smem);
    load_stage(sb, 0, r0, t);
    CP_ASYNC_COMMIT();

    for (int it = 0; it < TOTAL_IT; it++) {
        if (it + 1 < TOTAL_IT) {
            load_stage(sb + ((it + 1) & 1) * STAGE_BYTES, it + 1, r0, t);
            CP_ASYNC_COMMIT();
            CP_ASYNC_WAIT1();
        } else {
            CP_ASYNC_WAIT0();
        }
        __syncthreads();

        {
            char* stc = smem + (it & 1) * STAGE_BYTES;
            const float* Ah = (const float*)(stc + OFF_AH);
            const float* Al = (const float*)(stc + OFF_AL);
            const float* Bh = (const float*)(stc + OFF_BH);
            const float* Bl = (const float*)(stc + OFF_BL);
            const int ar0 = warp_m * 32 + q;
            const int bcol = q * 16 + warp_n * 8;
#pragma unroll
            for (int k8 = 0; k8 < 4; k8++) {
                const int kb = k8 * 8;
                float2 ah[2][2], al2[2][2];
#pragma unroll
                for (int mt = 0; mt < 2; mt++)
#pragma unroll
                    for (int h = 0; h < 2; h++) {
                        int r = (ar0 + mt * 16 + 8 * h) * A_STRIDE + kb + 2 * c4;
                        ah[mt][h]  = *(const float2*)&Ah[r];
                        al2[mt][h] = *(const float2*)&Al[r];
                    }
                float4 bh[2][2], bl[2][2];   // [k half][nt group]
#pragma unroll
                for (int kk = 0; kk < 2; kk++) {
                    int rb = (kb + c4 + 4 * kk) * B_STRIDE + bcol;
                    bh[kk][0] = *(const float4*)&Bh[rb];
                    bh[kk][1] = *(const float4*)&Bh[rb + 4];
                    bl[kk][0] = *(const float4*)&Bl[rb];
                    bl[kk][1] = *(const float4*)&Bl[rb + 4];
                }
#pragma unroll
                for (int mt = 0; mt < 2; mt++) {
                    uint32_t A0h = fb(ah[mt][0].x),  A1h = fb(ah[mt][1].x);
                    uint32_t A2h = fb(ah[mt][0].y),  A3h = fb(ah[mt][1].y);
                    uint32_t A0l = fb(al2[mt][0].x), A1l = fb(al2[mt][1].x);
                    uint32_t A2l = fb(al2[mt][0].y), A3l = fb(al2[mt][1].y);
#pragma unroll
                    for (int nt = 0; nt < 8; nt++) {
                        uint32_t b0h = fb(((const float*)&bh[0][nt >> 2])[nt & 3]);
                        uint32_t b1h = fb(((const float*)&bh[1][nt >> 2])[nt & 3]);
                        uint32_t b0l = fb(((const float*)&bl[0][nt >> 2])[nt & 3]);
                        uint32_t b1l = fb(((const float*)&bl[1][nt >> 2])[nt & 3]);
                        float* C = acc[mt][nt];
                        MMA_TF32(C, A0h, A1h, A2h, A3h, b0h, b1h);
                        MMA_TF32(C, A0h, A1h, A2h, A3h, b0l, b1l);
                        MMA_TF32(C, A0l, A1l, A2l, A3l, b0h, b1h);
                    }
                }
            }
        }

        // fold argmin at end of each code tile
        if ((it & 15) == 15) {
            const int c0t = (it >> 4) * BC;
#pragma unroll
            for (int nt = 0; nt < 8; nt++) {
                int col = warp_n * 64 + nt * 8 + 2 * c4;
                float w20 = __ldg(&g_w2[c0t + col]);
                float w21 = __ldg(&g_w2[c0t + col + 1]);
#pragma unroll
                for (int mt = 0; mt < 2; mt++) {
                    float s0 = fmaf(-2.f, acc[mt][nt][0], w20);
                    float s1 = fmaf(-2.f, acc[mt][nt][1], w21);
                    float s2 = fmaf(-2.f, acc[mt][nt][2], w20);
                    float s3 = fmaf(-2.f, acc[mt][nt][3], w21);
                    if (s0 < best[mt][0]) { best[mt][0] = s0; bidx[mt][0] = c0t + col; }
                    if (s1 < best[mt][0]) { best[mt][0] = s1; bidx[mt][0] = c0t + col + 1; }
                    if (s2 < best[mt][1]) { best[mt][1] = s2; bidx[mt][1] = c0t + col; }
                    if (s3 < best[mt][1]) { best[mt][1] = s3; bidx[mt][1] = c0t + col + 1; }
                    acc[mt][nt][0] = acc[mt][nt][1] = acc[mt][nt][2] = acc[mt][nt][3] = 0.f;
                }
            }
        }
        __syncthreads();
    }

    // final reduction: 4 lanes sharing a row, then 2 warp_n halves via SMEM
    float* rv = (float*)(smem + SM_RED);
    int*   ri = (int*)(smem + SM_RED + 2048);
#pragma unroll
    for (int mt = 0; mt < 2; mt++)
#pragma unroll
        for (int h = 0; h < 2; h++) {
            float v = best[mt][h];
            int   i = bidx[mt][h];
#pragma unroll
            for (int m = 1; m <= 2; m <<= 1) {
                float ov = __shfl_xor_sync(0xffffffffu, v, m);
                int   oi = __shfl_xor_sync(0xffffffffu, i, m);
                if (ov < v || (ov == v && oi < i)) { v = ov; i = oi; }
            }
            if (c4 == 0) {
                int row = warp_m * 32 + mt * 16 + q + 8 * h;
                rv[warp_n * 128 + row] = v;
                ri[warp_n * 128 + row] = i;
            }
        }
    __syncthreads();
    if (t < 128) {
        float v0 = rv[t], v1 = rv[128 + t];
        int   i0 = ri[t], i1 = ri[128 + t];
        if (v1 < v0 || (v1 == v0 && i1 < i0)) { v0 = v1; i0 = i1; }
        g_idx[r0 + t] = i0;
    }
}

// ---------------------------------------------------------------------------
// Gather z_q, outputs, per-row loss, histogram
// out layout: [z_q_real N*D][z_q_imag N*D][loss N][idx N][entropy 1]
// ---------------------------------------------------------------------------
__global__ void gather_kernel(const float* __restrict__ zr, const float* __restrict__ zi,
                              const float* __restrict__ w, float* __restrict__ out) {
    int row  = blockIdx.x * 8 + (threadIdx.x >> 5);
    int lane = threadIdx.x & 31;
    if (row >= N_ROWS) return;

    int ci = g_idx[row];
    const float* wrow = w + (size_t)ci * KDIM;
    float ss = 0.f;
#pragma unroll
    for (int p = 0; p < DHALF / 32; p++) {
        int d = lane + p * 32;
        float wv = wrow[d];
        float zv = zr[(size_t)row * DHALF + d];
        out[(size_t)row * DHALF + d] = wv;
        float df = wv - zv;
        ss = fmaf(df, df, ss);
    }
#pragma unroll
    for (int p = 0; p < DHALF / 32; p++) {
        int d = lane + p * 32;
        float wv = wrow[DHALF + d];
        float zv = zi[(size_t)row * DHALF + d];
        out[(size_t)N_ROWS * DHALF + (size_t)row * DHALF + d] = wv;
        float df = wv - zv;
        ss = fmaf(df, df, ss);
    }
#pragma unroll
    for (int m = 16; m >= 1; m >>= 1) ss += __shfl_xor_sync(0xffffffffu, ss, m);
    if (lane == 0) {
        size_t base = (size_t)2 * N_ROWS * DHALF;
        out[base + row] = ss * (1.25f / (float)KDIM);
        out[base + N_ROWS + row] = (float)ci;
        atomicAdd(&g_counts[ci], 1);
    }
}

__global__ void entropy_kernel(float* __restrict__ out) {
    __shared__ float red[1024];
    int t = threadIdx.x;
    float s = 0.f;
    for (int v = t; v < VCODES; v += 1024) {
        float p = (float)g_counts[v] * (1.f / (float)N_ROWS);
        s += p * logf(p + 1e-10f);
    }
    red[t] = s;
    __syncthreads();
    for (int m = 512; m >= 1; m >>= 1) {
        if (t < m) red[t] += red[t + m];
        __syncthreads();
    }
    if (t == 0) out[(size_t)2 * N_ROWS * DHALF + 2 * N_ROWS] = -red[0];
}

// ---------------------------------------------------------------------------
extern "C" void kernel_launch(void* const* d_in, const int* in_sizes, int n_in,
                              void* d_out, int out_size) {
    const float* zr = (const float*)d_in[0];
    const float* zi = (const float*)d_in[1];
    const float* w  = (const float*)d_in[2];
    float* out = (float*)d_out;

    cudaFuncSetAttribute(argmin_mma_kernel,
                         cudaFuncAttributeMaxDynamicSharedMemorySize, SMEM_TOTAL);

    split_z_kernel<<<(N_ROWS * KDIM + 255) / 256, 256>>>(zr, zi);
    split_w_kernel<<<dim3(VCODES / 128, K_CHUNKS), 256>>>(w);
    w2_kernel<<<VCODES / 8, 256>>>(w);
    zero_counts_kernel<<<(VCODES + 1023) / 1024, 1024>>>();
    argmin_mma_kernel<<<N_ROWS / BR, NTHREADS, SMEM_TOTAL>>>();
    gather_kernel<<<N_ROWS / 8, 256>>>(zr, zi, w, out);
    entropy_kernel<<<1, 1024>>>(out);
}

// round 4
// speedup vs baseline: 2.1487x; 1.6921x over previous
#include <cuda_runtime.h>
#include <cstdint>
#include <math.h>

// Problem constants
#define N_ROWS 16384
#define DHALF  256
#define KDIM   512
#define VCODES 8192

// GEMM tiling
#define BR 128
#define BC 128
#define KC 32
#define N_TILES  (VCODES / BC)        // 64
#define K_CHUNKS (KDIM / KC)          // 16
#define TOTAL_IT (N_TILES * K_CHUNKS) // 1024
#define NTHREADS 256

// Rescore margin: tf32-prune error sigma ~1.5e-3; 0.05 is >30 sigma.
#define MARGIN 0.05f

// SMEM stage layout (floats): A[128][40], B[32][136], hi only, double buffered
#define A_STRIDE 40
#define B_STRIDE 136
#define A_BYTES (128 * A_STRIDE * 4)              // 20480
#define B_BYTES (KC * B_STRIDE * 4)               // 17408
#define OFF_AH 0
#define OFF_BH (A_BYTES)
#define STAGE_BYTES (A_BYTES + B_BYTES)           // 37888
#define SMEM_TOTAL (2 * STAGE_BYTES)              // 75776

// Scratch globals (no allocations allowed)
__device__ float g_w2[VCODES];
__device__ int   g_counts[VCODES];
__device__ int   g_idx[N_ROWS];
// z hi: [row][512], k permuted within each 8-block: k%8 -> 2*(k%4) + (k%8)/4
__device__ float g_z_hi[(size_t)N_ROWS * KDIM];
// w hi: [tile(64)][k(512)][col(128) permuted: p = (n%128)/8 + 16*(n%8)]
__device__ float g_w_hi[(size_t)VCODES * KDIM];
// approximate score matrix (pass 1 output)
__device__ float g_scores[(size_t)N_ROWS * VCODES];

// ---------------------------------------------------------------------------
__device__ __forceinline__ uint32_t smem_u32(const void* p) {
    uint32_t a;
    asm("{ .reg .u64 t; cvta.to.shared.u64 t, %1; cvt.u32.u64 %0, t; }" : "=r"(a) : "l"(p));
    return a;
}
#define CP_ASYNC16(dst, src) \
    asm volatile("cp.async.cg.shared.global [%0], [%1], 16;" :: "r"(dst), "l"(src) : "memory")
#define CP_ASYNC_COMMIT() asm volatile("cp.async.commit_group;" ::: "memory")
#define CP_ASYNC_WAIT0()  asm volatile("cp.async.wait_group 0;" ::: "memory")
#define CP_ASYNC_WAIT1()  asm volatile("cp.async.wait_group 1;" ::: "memory")

#define MMA_TF32(C, a0, a1, a2, a3, b0, b1) \
    asm volatile("mma.sync.aligned.m16n8k8.row.col.f32.tf32.tf32.f32 " \
        "{%0,%1,%2,%3}, {%4,%5,%6,%7}, {%8,%9}, {%0,%1,%2,%3};" \
        : "+f"((C)[0]), "+f"((C)[1]), "+f"((C)[2]), "+f"((C)[3]) \
        : "r"(a0), "r"(a1), "r"(a2), "r"(a3), "r"(b0), "r"(b1))

__device__ __forceinline__ float to_tf32(float x) {
    uint32_t r;
    asm("cvt.rna.tf32.f32 %0, %1;" : "=r"(r) : "f"(x));
    return __uint_as_float(r);
}
__device__ __forceinline__ uint32_t fb(float x) { return __float_as_uint(x); }

// ---------------------------------------------------------------------------
// Split + permute z (hi only)
// ---------------------------------------------------------------------------
__global__ void split_z_kernel(const float* __restrict__ zr, const float* __restrict__ zi) {
    int q = blockIdx.x * blockDim.x + threadIdx.x;
    if (q >= N_ROWS * KDIM) return;
    int row = q >> 9, k = q & 511;
    float v = (k < DHALF) ? zr[(size_t)row * DHALF + k] : zi[(size_t)row * DHALF + k - DHALF];
    int kp = (k & ~7) | ((k & 3) << 1) | ((k >> 2) & 1);
    g_z_hi[(size_t)row * KDIM + kp] = to_tf32(v);
}

// ---------------------------------------------------------------------------
// Split + transpose + permute w (hi only) into [tile][k][pcol]
// ---------------------------------------------------------------------------
__global__ void split_w_kernel(const float* __restrict__ w) {
    __shared__ float tile[128][33];
    int ct = blockIdx.x, kt = blockIdx.y;
    int t = threadIdx.x;
#pragma unroll
    for (int p = 0; p < 4; p++) {
        int e = t + p * 256;
        int r = e >> 3, g = e & 7;
        float4 v = *(const float4*)&w[(size_t)(ct * 128 + r) * KDIM + kt * 32 + g * 4];
        tile[r][g * 4 + 0] = v.x; tile[r][g * 4 + 1] = v.y;
        tile[r][g * 4 + 2] = v.z; tile[r][g * 4 + 3] = v.w;
    }
    __syncthreads();
#pragma unroll
    for (int p = 0; p < 16; p++) {
        int e = t + p * 256;
        int k = e >> 7, pc = e & 127;
        int n = (pc & 15) * 8 + (pc >> 4);            // inverse permutation
        float v = tile[n][k];
        size_t d = (size_t)ct * (KDIM * 128) + (size_t)(kt * 32 + k) * 128 + pc;
        g_w_hi[d] = to_tf32(v);
    }
}

// ---------------------------------------------------------------------------
__global__ void w2_kernel(const float* __restrict__ w) {
    int v = blockIdx.x * 8 + (threadIdx.x >> 5);
    int lane = threadIdx.x & 31;
    if (v >= VCODES) return;
    const float* wr = w + (size_t)v * KDIM;
    float s = 0.f;
#pragma unroll
    for (int p = 0; p < KDIM / 32; p++) { float x = wr[lane + p * 32]; s = fmaf(x, x, s); }
#pragma unroll
    for (int m = 16; m >= 1; m >>= 1) s += __shfl_xor_sync(0xffffffffu, s, m);
    if (lane == 0) g_w2[v] = s;
}

__global__ void zero_counts_kernel() {
    int i = blockIdx.x * blockDim.x + threadIdx.x;
    if (i < VCODES) g_counts[i] = 0;
}

// ---------------------------------------------------------------------------
// Stage loader: A 128x32 + B 32x128 (hi only) via cp.async
// ---------------------------------------------------------------------------
__device__ __forceinline__ void load_stage(uint32_t st, int it, int r0, int t) {
    const int ct = it >> 4, kc = it & 15;
    const int k0 = kc * KC;
#pragma unroll
    for (int p = 0; p < 4; p++) {
        int e = t + p * NTHREADS;
        int row = e >> 3, g = e & 7;
        uint32_t doff = (uint32_t)(row * (A_STRIDE * 4) + g * 16);
        CP_ASYNC16(st + OFF_AH + doff, &g_z_hi[(size_t)(r0 + row) * KDIM + k0 + g * 4]);
    }
#pragma unroll
    for (int p = 0; p < 4; p++) {
        int e = t + p * NTHREADS;
        int kr = e >> 5, c = e & 31;
        uint32_t doff = (uint32_t)(kr * (B_STRIDE * 4) + c * 16);
        CP_ASYNC16(st + OFF_BH + doff,
                   &g_w_hi[(size_t)ct * (KDIM * 128) + (size_t)(k0 + kr) * 128 + c * 4]);
    }
}

// ---------------------------------------------------------------------------
// Pass 1: 1xTF32 mma.sync GEMM, write approximate score matrix
// ---------------------------------------------------------------------------
__global__ __launch_bounds__(NTHREADS, 1)
void score_mma_kernel() {
    extern __shared__ char smem[];
    const int t = threadIdx.x;
    const int wid = t >> 5, lane = t & 31;
    const int warp_m = wid & 3, warp_n = wid >> 2;
    const int q = lane >> 2, c4 = lane & 3;
    const int r0 = blockIdx.x * BR;

    float acc[2][8][4];
#pragma unroll
    for (int mt = 0; mt < 2; mt++)
#pragma unroll
        for (int nt = 0; nt < 8; nt++)
#pragma unroll
            for (int j = 0; j < 4; j++) acc[mt][nt][j] = 0.f;

    const uint32_t sb = smem_u32(smem);
    load_stage(sb, 0, r0, t);
    CP_ASYNC_COMMIT();

    for (int it = 0; it < TOTAL_IT; it++) {
        if (it + 1 < TOTAL_IT) {
            load_stage(sb + ((it + 1) & 1) * STAGE_BYTES, it + 1, r0, t);
            CP_ASYNC_COMMIT();
            CP_ASYNC_WAIT1();
        } else {
            CP_ASYNC_WAIT0();
        }
        __syncthreads();

        {
            char* stc = smem + (it & 1) * STAGE_BYTES;
            const float* Ah = (const float*)(stc + OFF_AH);
            const float* Bh = (const float*)(stc + OFF_BH);
            const int ar0 = warp_m * 32 + q;
            const int bcol = q * 16 + warp_n * 8;
#pragma unroll
            for (int k8 = 0; k8 < 4; k8++) {
                const int kb = k8 * 8;
                float2 ah[2][2];
#pragma unroll
                for (int mt = 0; mt < 2; mt++)
#pragma unroll
                    for (int h = 0; h < 2; h++)
                        ah[mt][h] = *(const float2*)&Ah[(ar0 + mt * 16 + 8 * h) * A_STRIDE + kb + 2 * c4];
                float4 bh[2][2];   // [k half][nt group]
#pragma unroll
                for (int kk = 0; kk < 2; kk++) {
                    int rb = (kb + c4 + 4 * kk) * B_STRIDE + bcol;
                    bh[kk][0] = *(const float4*)&Bh[rb];
                    bh[kk][1] = *(const float4*)&Bh[rb + 4];
                }
#pragma unroll
                for (int mt = 0; mt < 2; mt++) {
                    uint32_t A0 = fb(ah[mt][0].x), A1 = fb(ah[mt][1].x);
                    uint32_t A2 = fb(ah[mt][0].y), A3 = fb(ah[mt][1].y);
#pragma unroll
                    for (int nt = 0; nt < 8; nt++) {
                        uint32_t b0 = fb(((const float*)&bh[0][nt >> 2])[nt & 3]);
                        uint32_t b1 = fb(((const float*)&bh[1][nt >> 2])[nt & 3]);
                        MMA_TF32(acc[mt][nt], A0, A1, A2, A3, b0, b1);
                    }
                }
            }
        }

        // end of code tile: write scores, reset accumulators
        if ((it & 15) == 15) {
            const int c0t = (it >> 4) * BC;
#pragma unroll
            for (int nt = 0; nt < 8; nt++) {
                int col = warp_n * 64 + nt * 8 + 2 * c4;
                float w20 = __ldg(&g_w2[c0t + col]);
                float w21 = __ldg(&g_w2[c0t + col + 1]);
#pragma unroll
                for (int mt = 0; mt < 2; mt++) {
                    int row = r0 + warp_m * 32 + mt * 16 + q;
                    float2 s01 = make_float2(fmaf(-2.f, acc[mt][nt][0], w20),
                                             fmaf(-2.f, acc[mt][nt][1], w21));
                    float2 s23 = make_float2(fmaf(-2.f, acc[mt][nt][2], w20),
                                             fmaf(-2.f, acc[mt][nt][3], w21));
                    *(float2*)&g_scores[(size_t)row * VCODES + c0t + col] = s01;
                    *(float2*)&g_scores[(size_t)(row + 8) * VCODES + c0t + col] = s23;
                    acc[mt][nt][0] = acc[mt][nt][1] = acc[mt][nt][2] = acc[mt][nt][3] = 0.f;
                }
            }
        }
        __syncthreads();
    }
}

// ---------------------------------------------------------------------------
// Pass 2: per-row scan of approx scores; exact fp32 rescore of candidates
// within MARGIN of the approx minimum. One warp per row.
// ---------------------------------------------------------------------------
__global__ __launch_bounds__(256)
void scan_rescore_kernel(const float* __restrict__ zr, const float* __restrict__ zi,
                         const float* __restrict__ w) {
    int row  = blockIdx.x * 8 + (threadIdx.x >> 5);
    int lane = threadIdx.x & 31;
    if (row >= N_ROWS) return;
    const float* srow = &g_scores[(size_t)row * VCODES];

    // sweep 1: approximate minimum
    float m = 3.4e38f;
    for (int i = lane; i < VCODES; i += 32) {
        float v = srow[i];
        if (v < m) m = v;
    }
#pragma unroll
    for (int msk = 16; msk >= 1; msk >>= 1) m = fminf(m, __shfl_xor_sync(0xffffffffu, m, msk));
    const float thresh = m + MARGIN;

    // preload z row into registers (natural k order)
    float zreg[16];
#pragma unroll
    for (int p = 0; p < 16; p++) {
        int k = lane + 32 * p;
        zreg[p] = (k < DHALF) ? zr[(size_t)row * DHALF + k]
                              : zi[(size_t)row * DHALF + k - DHALF];
    }

    // sweep 2: rescore candidates exactly, ascending index (jnp.argmin tiebreak)
    float bv = 3.4e38f;
    int   bi = 0;
    for (int i = 0; i < VCODES / 32; i++) {
        float v = srow[lane + 32 * i];
        unsigned mask = __ballot_sync(0xffffffffu, v <= thresh);
        while (mask) {
            int j = __ffs(mask) - 1;
            mask &= mask - 1;
            int c = 32 * i + j;
            const float* wrow = &w[(size_t)c * KDIM];
            float dot = 0.f;
#pragma unroll
            for (int p = 0; p < 16; p++) dot = fmaf(zreg[p], wrow[lane + 32 * p], dot);
#pragma unroll
            for (int msk = 16; msk >= 1; msk >>= 1) dot += __shfl_xor_sync(0xffffffffu, dot, msk);
            float ex = fmaf(-2.f, dot, __ldg(&g_w2[c]));
            if (ex < bv) { bv = ex; bi = c; }       // strict < : first index wins ties
        }
    }
    if (lane == 0) g_idx[row] = bi;
}

// ---------------------------------------------------------------------------
// Gather z_q, outputs, per-row loss, histogram
// out layout: [z_q_real N*D][z_q_imag N*D][loss N][idx N][entropy 1]
// ---------------------------------------------------------------------------
__global__ void gather_kernel(const float* __restrict__ zr, const float* __restrict__ zi,
                              const float* __restrict__ w, float* __restrict__ out) {
    int row  = blockIdx.x * 8 + (threadIdx.x >> 5);
    int lane = threadIdx.x & 31;
    if (row >= N_ROWS) return;

    int ci = g_idx[row];
    const float* wrow = w + (size_t)ci * KDIM;
    float ss = 0.f;
#pragma unroll
    for (int p = 0; p < DHALF / 32; p++) {
        int d = lane + p * 32;
        float wv = wrow[d];
        float zv = zr[(size_t)row * DHALF + d];
        out[(size_t)row * DHALF + d] = wv;
        float df = wv - zv;
        ss = fmaf(df, df, ss);
    }
#pragma unroll
    for (int p = 0; p < DHALF / 32; p++) {
        int d = lane + p * 32;
        float wv = wrow[DHALF + d];
        float zv = zi[(size_t)row * DHALF + d];
        out[(size_t)N_ROWS * DHALF + (size_t)row * DHALF + d] = wv;
        float df = wv - zv;
        ss = fmaf(df, df, ss);
    }
#pragma unroll
    for (int m = 16; m >= 1; m >>= 1) ss += __shfl_xor_sync(0xffffffffu, ss, m);
    if (lane == 0) {
        size_t base = (size_t)2 * N_ROWS * DHALF;
        out[base + row] = ss * (1.25f / (float)KDIM);
        out[base + N_ROWS + row] = (float)ci;
        atomicAdd(&g_counts[ci], 1);
    }
}

__global__ void entropy_kernel(float* __restrict__ out) {
    __shared__ float red[1024];
    int t = threadIdx.x;
    float s = 0.f;
    for (int v = t; v < VCODES; v += 1024) {
        float p = (float)g_counts[v] * (1.f / (float)N_ROWS);
        s += p * logf(p + 1e-10f);
    }
    red[t] = s;
    __syncthreads();
    for (int m = 512; m >= 1; m >>= 1) {
        if (t < m) red[t] += red[t + m];
        __syncthreads();
    }
    if (t == 0) out[(size_t)2 * N_ROWS * DHALF + 2 * N_ROWS] = -red[0];
}

// ---------------------------------------------------------------------------
extern "C" void kernel_launch(void* const* d_in, const int* in_sizes, int n_in,
                              void* d_out, int out_size) {
    const float* zr = (const float*)d_in[0];
    const float* zi = (const float*)d_in[1];
    const float* w  = (const float*)d_in[2];
    float* out = (float*)d_out;

    cudaFuncSetAttribute(score_mma_kernel,
                         cudaFuncAttributeMaxDynamicSharedMemorySize, SMEM_TOTAL);

    split_z_kernel<<<(N_ROWS * KDIM + 255) / 256, 256>>>(zr, zi);
    split_w_kernel<<<dim3(VCODES / 128, K_CHUNKS), 256>>>(w);
    w2_kernel<<<VCODES / 8, 256>>>(w);
    zero_counts_kernel<<<(VCODES + 1023) / 1024, 1024>>>();
    score_mma_kernel<<<N_ROWS / BR, NTHREADS, SMEM_TOTAL>>>();
    scan_rescore_kernel<<<N_ROWS / 8, 256>>>(zr, zi, w);
    gather_kernel<<<N_ROWS / 8, 256>>>(zr, zi, w, out);
    entropy_kernel<<<1, 1024>>>(out);
}

// round 5
// speedup vs baseline: 4.7784x; 2.2239x over previous
#include <cuda_runtime.h>
#include <cuda_fp16.h>
#include <cstdint>
#include <math.h>

// Problem constants
#define N_ROWS 16384
#define DHALF  256
#define KDIM   512
#define VCODES 8192

// Tiling
#define BR 128
#define BC 128
#define KC 64                          // halves per stage
#define N_TILES  (VCODES / BC)         // 64
#define K_CHUNKS (KDIM / KC)           // 8
#define TOTAL_IT (N_TILES * K_CHUNKS)  // 512
#define NTHREADS 256

#define MARGIN 0.1f
#define CAP 48

// SMEM layout (bytes): A rows padded to 144B (72 halves) for conflict-free ldmatrix
#define A_STAGE 18432                  // 128*144
#define B_STAGE 18432
#define OFF_A0 0
#define OFF_A1 (A_STAGE)
#define OFF_B0 (2 * A_STAGE)
#define OFF_B1 (2 * A_STAGE + B_STAGE)
#define OFF_CAND (2 * A_STAGE + 2 * B_STAGE)          // 73728: uint16[128][2][CAP]
#define OFF_CNT  (OFF_CAND + 128 * 2 * CAP * 2)       // 98304: int[128][2]
#define SMEM_TOTAL (OFF_CNT + 1024)                   // 99328

// Scratch globals
__device__ float    g_w2[VCODES];
__device__ int      g_counts[VCODES];
__device__ int      g_idx[N_ROWS];
__device__ __half   g_z_h[(size_t)N_ROWS * KDIM];   // [row][512]
__device__ __half   g_w_h[(size_t)VCODES * KDIM];   // [code][512]

// ---------------------------------------------------------------------------
__device__ __forceinline__ uint32_t smem_u32(const void* p) {
    uint32_t a;
    asm("{ .reg .u64 t; cvta.to.shared.u64 t, %1; cvt.u32.u64 %0, t; }" : "=r"(a) : "l"(p));
    return a;
}
#define CP_ASYNC16(dst, src) \
    asm volatile("cp.async.cg.shared.global [%0], [%1], 16;" :: "r"(dst), "l"(src) : "memory")
#define CP_ASYNC_COMMIT() asm volatile("cp.async.commit_group;" ::: "memory")
#define CP_ASYNC_WAIT0()  asm volatile("cp.async.wait_group 0;" ::: "memory")
#define CP_ASYNC_WAIT1()  asm volatile("cp.async.wait_group 1;" ::: "memory")

#define LDSM_X4(r0, r1, r2, r3, addr) \
    asm volatile("ldmatrix.sync.aligned.m8n8.x4.shared.b16 {%0,%1,%2,%3}, [%4];" \
        : "=r"(r0), "=r"(r1), "=r"(r2), "=r"(r3) : "r"(addr))

#define MMA_F16(C, a0, a1, a2, a3, b0, b1) \
    asm volatile("mma.sync.aligned.m16n8k16.row.col.f32.f16.f16.f32 " \
        "{%0,%1,%2,%3}, {%4,%5,%6,%7}, {%8,%9}, {%0,%1,%2,%3};" \
        : "+f"((C)[0]), "+f"((C)[1]), "+f"((C)[2]), "+f"((C)[3]) \
        : "r"(a0), "r"(a1), "r"(a2), "r"(a3), "r"(b0), "r"(b1))

// ---------------------------------------------------------------------------
// f32 -> f16 converts (natural layouts, no transpose)
// ---------------------------------------------------------------------------
__global__ void conv_z_kernel(const float* __restrict__ zr, const float* __restrict__ zi) {
    int q = blockIdx.x * blockDim.x + threadIdx.x;           // float4 index
    if (q >= N_ROWS * KDIM / 4) return;
    int row = q >> 7, kq = (q & 127) * 4;
    float4 v = (kq < DHALF) ? *(const float4*)&zr[(size_t)row * DHALF + kq]
                            : *(const float4*)&zi[(size_t)row * DHALF + kq - DHALF];
    __half2 h0 = __floats2half2_rn(v.x, v.y);
    __half2 h1 = __floats2half2_rn(v.z, v.w);
    *(__half2*)&g_z_h[(size_t)row * KDIM + kq] = h0;
    *(__half2*)&g_z_h[(size_t)row * KDIM + kq + 2] = h1;
}

__global__ void conv_w_kernel(const float* __restrict__ w) {
    int q = blockIdx.x * blockDim.x + threadIdx.x;
    if (q >= VCODES * KDIM / 4) return;
    float4 v = ((const float4*)w)[q];
    __half2 h0 = __floats2half2_rn(v.x, v.y);
    __half2 h1 = __floats2half2_rn(v.z, v.w);
    *(__half2*)&g_w_h[(size_t)q * 4] = h0;
    *(__half2*)&g_w_h[(size_t)q * 4 + 2] = h1;
}

__global__ void w2_kernel(const float* __restrict__ w) {
    int v = blockIdx.x * 8 + (threadIdx.x >> 5);
    int lane = threadIdx.x & 31;
    if (v >= VCODES) return;
    const float* wr = w + (size_t)v * KDIM;
    float s = 0.f;
#pragma unroll
    for (int p = 0; p < KDIM / 32; p++) { float x = wr[lane + p * 32]; s = fmaf(x, x, s); }
#pragma unroll
    for (int m = 16; m >= 1; m >>= 1) s += __shfl_xor_sync(0xffffffffu, s, m);
    if (lane == 0) g_w2[v] = s;
}

__global__ void zero_counts_kernel() {
    int i = blockIdx.x * blockDim.x + threadIdx.x;
    if (i < VCODES) g_counts[i] = 0;
}

// ---------------------------------------------------------------------------
// Stage loader: A 128x64h + B 128x64h via cp.async (rows padded to 144B)
// ---------------------------------------------------------------------------
__device__ __forceinline__ void load_stage(uint32_t sa, uint32_t sbb, int it, int r0, int t) {
    const int ct = it >> 3, kc = it & 7;
    const int k0 = kc * KC;
#pragma unroll
    for (int p = 0; p < 4; p++) {
        int e = t + p * NTHREADS;
        int row = e >> 3, g = e & 7;
        CP_ASYNC16(sa + (uint32_t)(row * 144 + g * 16),
                   &g_z_h[(size_t)(r0 + row) * KDIM + k0 + g * 8]);
    }
#pragma unroll
    for (int p = 0; p < 4; p++) {
        int e = t + p * NTHREADS;
        int row = e >> 3, g = e & 7;
        CP_ASYNC16(sbb + (uint32_t)(row * 144 + g * 16),
                   &g_w_h[(size_t)(ct * 128 + row) * KDIM + k0 + g * 8]);
    }
}

// ---------------------------------------------------------------------------
// Fused: f16 MMA prune -> per-row candidate lists -> exact fp32 rescore
// ---------------------------------------------------------------------------
__global__ __launch_bounds__(NTHREADS, 1)
void vq_mma_kernel(const float* __restrict__ zr, const float* __restrict__ zi,
                   const float* __restrict__ w) {
    extern __shared__ char smem[];
    const uint32_t sb = smem_u32(smem);
    const int t = threadIdx.x;
    const int wid = t >> 5, lane = t & 31;
    const int warp_m = wid & 3, warp_n = wid >> 2;
    const int q = lane >> 2, c4 = lane & 3;
    const int r0 = blockIdx.x * BR;

    uint16_t* cand = (uint16_t*)(smem + OFF_CAND);
    int*      cnt  = (int*)(smem + OFF_CNT);
    cnt[t] = 0;                                   // exactly 256 counters

    float acc[2][8][4];
#pragma unroll
    for (int mt = 0; mt < 2; mt++)
#pragma unroll
        for (int nt = 0; nt < 8; nt++)
#pragma unroll
            for (int j = 0; j < 4; j++) acc[mt][nt][j] = 0.f;
    float run[4] = {3.4e38f, 3.4e38f, 3.4e38f, 3.4e38f};

    load_stage(sb + OFF_A0, sb + OFF_B0, 0, r0, t);
    CP_ASYNC_COMMIT();
    __syncthreads();                              // cnt zeroing visible

    for (int it = 0; it < TOTAL_IT; it++) {
        if (it + 1 < TOTAL_IT) {
            const uint32_t sa = sb + (((it + 1) & 1) ? OFF_A1 : OFF_A0);
            const uint32_t sB = sb + (((it + 1) & 1) ? OFF_B1 : OFF_B0);
            load_stage(sa, sB, it + 1, r0, t);
            CP_ASYNC_COMMIT();
            CP_ASYNC_WAIT1();
        } else {
            CP_ASYNC_WAIT0();
        }
        __syncthreads();

        {
            const uint32_t sa = sb + ((it & 1) ? OFF_A1 : OFF_A0);
            const uint32_t sB = sb + ((it & 1) ? OFF_B1 : OFF_B0);
#pragma unroll
            for (int kb = 0; kb < 4; kb++) {
                uint32_t a[2][4];
#pragma unroll
                for (int mt = 0; mt < 2; mt++) {
                    uint32_t row = warp_m * 32 + mt * 16 + (lane & 15);
                    uint32_t koff = kb * 16 + ((lane & 16) ? 8 : 0);
                    LDSM_X4(a[mt][0], a[mt][1], a[mt][2], a[mt][3],
                            sa + row * 144 + koff * 2);
                }
#pragma unroll
                for (int ntp = 0; ntp < 4; ntp++) {
                    uint32_t n = warp_n * 64 + ntp * 16 + (lane & 7) + ((lane & 16) ? 8 : 0);
                    uint32_t koff = kb * 16 + ((lane & 8) ? 8 : 0);
                    uint32_t b0, b1, b2, b3;
                    LDSM_X4(b0, b1, b2, b3, sB + n * 144 + koff * 2);
#pragma unroll
                    for (int mt = 0; mt < 2; mt++) {
                        MMA_F16(acc[mt][2 * ntp],     a[mt][0], a[mt][1], a[mt][2], a[mt][3], b0, b1);
                        MMA_F16(acc[mt][2 * ntp + 1], a[mt][0], a[mt][1], a[mt][2], a[mt][3], b2, b3);
                    }
                }
            }
        }

        // ---- tile boundary: scores, running min, candidate append ----
        if ((it & 7) == 7) {
            const int c0t = (it >> 3) * BC;
            float w2v[8][2];
#pragma unroll
            for (int nt = 0; nt < 8; nt++) {
                int c = c0t + warp_n * 64 + nt * 8 + 2 * c4;
                w2v[nt][0] = __ldg(&g_w2[c]);
                w2v[nt][1] = __ldg(&g_w2[c + 1]);
            }
#pragma unroll
            for (int rr = 0; rr < 4; rr++) {
                const int mt = rr >> 1, h = rr & 1;
                float s[16];
#pragma unroll
                for (int nt = 0; nt < 8; nt++) {
                    s[2 * nt]     = fmaf(-2.f, acc[mt][nt][2 * h],     w2v[nt][0]);
                    s[2 * nt + 1] = fmaf(-2.f, acc[mt][nt][2 * h + 1], w2v[nt][1]);
                }
                float m = s[0];
#pragma unroll
                for (int j = 1; j < 16; j++) m = fminf(m, s[j]);
                m = fminf(m, __shfl_xor_sync(0xffffffffu, m, 1));
                m = fminf(m, __shfl_xor_sync(0xffffffffu, m, 2));
                run[rr] = fminf(run[rr], m);
                const float thr = run[rr] + MARGIN;
                const int rowl = warp_m * 32 + mt * 16 + h * 8 + q;
#pragma unroll
                for (int nt = 0; nt < 8; nt++) {
#pragma unroll
                    for (int j = 0; j < 2; j++) {
                        if (s[2 * nt + j] <= thr) {
                            int pos = atomicAdd(&cnt[rowl * 2 + warp_n], 1);
                            if (pos < CAP)
                                cand[(rowl * 2 + warp_n) * CAP + pos] =
                                    (uint16_t)(c0t + warp_n * 64 + nt * 8 + 2 * c4 + j);
                        }
                    }
                }
            }
            // reset accumulators
#pragma unroll
            for (int mt = 0; mt < 2; mt++)
#pragma unroll
                for (int nt = 0; nt < 8; nt++)
#pragma unroll
                    for (int j = 0; j < 4; j++) acc[mt][nt][j] = 0.f;
        }
        __syncthreads();
    }

    // ---- exact fp32 rescore of candidates (one warp per 16 rows) ----
    for (int j = 0; j < 16; j++) {
        const int rowl = wid * 16 + j;
        const int grow = r0 + rowl;
        float zreg[16];
#pragma unroll
        for (int p = 0; p < 16; p++) {
            int k = lane + 32 * p;
            zreg[p] = (k < DHALF) ? zr[(size_t)grow * DHALF + k]
                                  : zi[(size_t)grow * DHALF + k - DHALF];
        }
        int n0 = min(cnt[rowl * 2], CAP);
        int n1 = min(cnt[rowl * 2 + 1], CAP);
        float bv = 3.4e38f;
        int   bi = 0x7fffffff;
        for (int tt = 0; tt < n0 + n1; tt++) {
            int code = (tt < n0) ? cand[(rowl * 2) * CAP + tt]
                                 : cand[(rowl * 2 + 1) * CAP + tt - n0];
            const float* wrow = &w[(size_t)code * KDIM];
            float dot = 0.f;
#pragma unroll
            for (int p = 0; p < 16; p++) dot = fmaf(zreg[p], wrow[lane + 32 * p], dot);
#pragma unroll
            for (int m = 16; m >= 1; m >>= 1) dot += __shfl_xor_sync(0xffffffffu, dot, m);
            float ex = fmaf(-2.f, dot, __ldg(&g_w2[code]));
            if (ex < bv || (ex == bv && code < bi)) { bv = ex; bi = code; }
        }
        if (lane == 0) g_idx[grow] = bi;
    }
}

// ---------------------------------------------------------------------------
// Gather z_q, outputs, per-row loss, histogram
// out layout: [z_q_real N*D][z_q_imag N*D][loss N][idx N][entropy 1]
// ---------------------------------------------------------------------------
__global__ void gather_kernel(const float* __restrict__ zr, const float* __restrict__ zi,
                              const float* __restrict__ w, float* __restrict__ out) {
    int row  = blockIdx.x * 8 + (threadIdx.x >> 5);
    int lane = threadIdx.x & 31;
    if (row >= N_ROWS) return;

    int ci = g_idx[row];
    const float* wrow = w + (size_t)ci * KDIM;
    float ss = 0.f;
#pragma unroll
    for (int p = 0; p < DHALF / 32; p++) {
        int d = lane + p * 32;
        float wv = wrow[d];
        float zv = zr[(size_t)row * DHALF + d];
        out[(size_t)row * DHALF + d] = wv;
        float df = wv - zv;
        ss = fmaf(df, df, ss);
    }
#pragma unroll
    for (int p = 0; p < DHALF / 32; p++) {
        int d = lane + p * 32;
        float wv = wrow[DHALF + d];
        float zv = zi[(size_t)row * DHALF + d];
        out[(size_t)N_ROWS * DHALF + (size_t)row * DHALF + d] = wv;
        float df = wv - zv;
        ss = fmaf(df, df, ss);
    }
#pragma unroll
    for (int m = 16; m >= 1; m >>= 1) ss += __shfl_xor_sync(0xffffffffu, ss, m);
    if (lane == 0) {
        size_t base = (size_t)2 * N_ROWS * DHALF;
        out[base + row] = ss * (1.25f / (float)KDIM);
        out[base + N_ROWS + row] = (float)ci;
        atomicAdd(&g_counts[ci], 1);
    }
}

__global__ void entropy_kernel(float* __restrict__ out) {
    __shared__ float red[1024];
    int t = threadIdx.x;
    float s = 0.f;
    for (int v = t; v < VCODES; v += 1024) {
        float p = (float)g_counts[v] * (1.f / (float)N_ROWS);
        s += p * logf(p + 1e-10f);
    }
    red[t] = s;
    __syncthreads();
    for (int m = 512; m >= 1; m >>= 1) {
        if (t < m) red[t] += red[t + m];
        __syncthreads();
    }
    if (t == 0) out[(size_t)2 * N_ROWS * DHALF + 2 * N_ROWS] = -red[0];
}

// ---------------------------------------------------------------------------
extern "C" void kernel_launch(void* const* d_in, const int* in_sizes, int n_in,
                              void* d_out, int out_size) {
    const float* zr = (const float*)d_in[0];
    const float* zi = (const float*)d_in[1];
    const float* w  = (const float*)d_in[2];
    float* out = (float*)d_out;

    cudaFuncSetAttribute(vq_mma_kernel,
                         cudaFuncAttributeMaxDynamicSharedMemorySize, SMEM_TOTAL);

    conv_z_kernel<<<(N_ROWS * KDIM / 4 + 255) / 256, 256>>>(zr, zi);
    conv_w_kernel<<<(VCODES * KDIM / 4 + 255) / 256, 256>>>(w);
    w2_kernel<<<VCODES / 8, 256>>>(w);
    zero_counts_kernel<<<(VCODES + 1023) / 1024, 1024>>>();
    vq_mma_kernel<<<N_ROWS / BR, NTHREADS, SMEM_TOTAL>>>(zr, zi, w);
    gather_kernel<<<N_ROWS / 8, 256>>>(zr, zi, w, out);
    entropy_kernel<<<1, 1024>>>(out);
}

// round 6
// speedup vs baseline: 6.6526x; 1.3922x over previous
#include <cuda_runtime.h>
#include <cstdint>
#include <math.h>

// Problem constants
#define N_ROWS 16384
#define DHALF  256
#define KDIM   512                     // bytes per row in s8 = floats per row
#define VCODES 8192

// Tiling
#define BR 128
#define BC 128
#define KCB 128                        // K bytes per stage
#define N_TILES  (VCODES / BC)         // 64
#define K_STAGES (KDIM / KCB)          // 4
#define TOTAL_IT (N_TILES * K_STAGES)  // 256
#define NTHREADS 256

#define MARGIN 0.5f
#define CAP 48

// SMEM: rows padded to 144B for conflict-free ldmatrix
#define A_STAGE 18432                  // 128*144
#define B_STAGE 18432
#define OFF_A0 0
#define OFF_A1 (A_STAGE)
#define OFF_B0 (2 * A_STAGE)
#define OFF_B1 (2 * A_STAGE + B_STAGE)
#define OFF_CAND (2 * A_STAGE + 2 * B_STAGE)          // uint16[128][2][CAP]
#define OFF_CNT  (OFF_CAND + 128 * 2 * CAP * 2)
#define SMEM_TOTAL (OFF_CNT + 1024)

// Scratch globals
__device__ float   g_w2[VCODES];
__device__ int     g_counts[VCODES];
__device__ int     g_idx[N_ROWS];
__device__ int     g_maxz;             // float-as-int (non-negative)
__device__ int     g_maxw;
__device__ int8_t  g_z8[(size_t)N_ROWS * KDIM];
__device__ int8_t  g_w8[(size_t)VCODES * KDIM];

// ---------------------------------------------------------------------------
__device__ __forceinline__ uint32_t smem_u32(const void* p) {
    uint32_t a;
    asm("{ .reg .u64 t; cvta.to.shared.u64 t, %1; cvt.u32.u64 %0, t; }" : "=r"(a) : "l"(p));
    return a;
}
#define CP_ASYNC16(dst, src) \
    asm volatile("cp.async.cg.shared.global [%0], [%1], 16;" :: "r"(dst), "l"(src) : "memory")
#define CP_ASYNC_COMMIT() asm volatile("cp.async.commit_group;" ::: "memory")
#define CP_ASYNC_WAIT0()  asm volatile("cp.async.wait_group 0;" ::: "memory")
#define CP_ASYNC_WAIT1()  asm volatile("cp.async.wait_group 1;" ::: "memory")

#define LDSM_X4(r0, r1, r2, r3, addr) \
    asm volatile("ldmatrix.sync.aligned.m8n8.x4.shared.b16 {%0,%1,%2,%3}, [%4];" \
        : "=r"(r0), "=r"(r1), "=r"(r2), "=r"(r3) : "r"(addr))

#define MMA_S8(C, a0, a1, a2, a3, b0, b1) \
    asm volatile("mma.sync.aligned.m16n8k32.row.col.s32.s8.s8.s32 " \
        "{%0,%1,%2,%3}, {%4,%5,%6,%7}, {%8,%9}, {%0,%1,%2,%3};" \
        : "+r"((C)[0]), "+r"((C)[1]), "+r"((C)[2]), "+r"((C)[3]) \
        : "r"(a0), "r"(a1), "r"(a2), "r"(a3), "r"(b0), "r"(b1))

// ---------------------------------------------------------------------------
__global__ void init_kernel() {
    int i = blockIdx.x * blockDim.x + threadIdx.x;
    if (i < VCODES) g_counts[i] = 0;
    if (i == 0) { g_maxz = 0; g_maxw = 0; }
}

// max |x| over a float array (n4 float4s); one atomic per warp
__global__ void maxabs_kernel(const float* __restrict__ p, int n4, int* __restrict__ dst) {
    int stride = gridDim.x * blockDim.x;
    float m = 0.f;
    for (int i = blockIdx.x * blockDim.x + threadIdx.x; i < n4; i += stride) {
        float4 v = ((const float4*)p)[i];
        m = fmaxf(m, fmaxf(fmaxf(fabsf(v.x), fabsf(v.y)), fmaxf(fabsf(v.z), fabsf(v.w))));
    }
#pragma unroll
    for (int s = 16; s >= 1; s >>= 1) m = fmaxf(m, __shfl_xor_sync(0xffffffffu, m, s));
    if ((threadIdx.x & 31) == 0) atomicMax(dst, __float_as_int(m));
}

// quantize z into [row][512] s8 (kq<256 -> zr)
__global__ void quant_z_kernel(const float* __restrict__ zr, const float* __restrict__ zi) {
    int q = blockIdx.x * blockDim.x + threadIdx.x;           // float4 index
    if (q >= N_ROWS * KDIM / 4) return;
    float inv = 127.f / __int_as_float(g_maxz);
    int row = q >> 7, kq = (q & 127) * 4;
    float4 v = (kq < DHALF) ? *(const float4*)&zr[(size_t)row * DHALF + kq]
                            : *(const float4*)&zi[(size_t)row * DHALF + kq - DHALF];
    char4 c;
    c.x = (char)__float2int_rn(v.x * inv);
    c.y = (char)__float2int_rn(v.y * inv);
    c.z = (char)__float2int_rn(v.z * inv);
    c.w = (char)__float2int_rn(v.w * inv);
    *(char4*)&g_z8[(size_t)row * KDIM + kq] = c;
}

__global__ void quant_w_kernel(const float* __restrict__ w) {
    int q = blockIdx.x * blockDim.x + threadIdx.x;
    if (q >= VCODES * KDIM / 4) return;
    float inv = 127.f / __int_as_float(g_maxw);
    float4 v = ((const float4*)w)[q];
    char4 c;
    c.x = (char)__float2int_rn(v.x * inv);
    c.y = (char)__float2int_rn(v.y * inv);
    c.z = (char)__float2int_rn(v.z * inv);
    c.w = (char)__float2int_rn(v.w * inv);
    *(char4*)&g_w8[(size_t)q * 4] = c;
}

__global__ void w2_kernel(const float* __restrict__ w) {
    int v = blockIdx.x * 8 + (threadIdx.x >> 5);
    int lane = threadIdx.x & 31;
    if (v >= VCODES) return;
    const float* wr = w + (size_t)v * KDIM;
    float s = 0.f;
#pragma unroll
    for (int p = 0; p < KDIM / 32; p++) { float x = wr[lane + p * 32]; s = fmaf(x, x, s); }
#pragma unroll
    for (int m = 16; m >= 1; m >>= 1) s += __shfl_xor_sync(0xffffffffu, s, m);
    if (lane == 0) g_w2[v] = s;
}

// ---------------------------------------------------------------------------
// Stage loader: A 128x128B + B 128x128B s8 via cp.async (rows padded to 144B)
// ---------------------------------------------------------------------------
__device__ __forceinline__ void load_stage(uint32_t sa, uint32_t sbb, int it, int r0, int t) {
    const int ct = it >> 2, kc = it & 3;
    const int k0 = kc * KCB;
#pragma unroll
    for (int p = 0; p < 4; p++) {
        int e = t + p * NTHREADS;
        int row = e >> 3, g = e & 7;
        CP_ASYNC16(sa + (uint32_t)(row * 144 + g * 16),
                   &g_z8[(size_t)(r0 + row) * KDIM + k0 + g * 16]);
    }
#pragma unroll
    for (int p = 0; p < 4; p++) {
        int e = t + p * NTHREADS;
        int row = e >> 3, g = e & 7;
        CP_ASYNC16(sbb + (uint32_t)(row * 144 + g * 16),
                   &g_w8[(size_t)(ct * 128 + row) * KDIM + k0 + g * 16]);
    }
}

// ---------------------------------------------------------------------------
// Fused: s8 IMMA prune -> candidate lists -> exact fp32 rescore
// ---------------------------------------------------------------------------
__global__ __launch_bounds__(NTHREADS, 1)
void vq_mma_kernel(const float* __restrict__ zr, const float* __restrict__ zi,
                   const float* __restrict__ w) {
    extern __shared__ char smem[];
    const uint32_t sb = smem_u32(smem);
    const int t = threadIdx.x;
    const int wid = t >> 5, lane = t & 31;
    const int warp_m = wid & 3, warp_n = wid >> 2;
    const int q = lane >> 2, c4 = lane & 3;
    const int r0 = blockIdx.x * BR;

    const float s2 = -2.f * (__int_as_float(g_maxz) / 127.f)
                          * (__int_as_float(g_maxw) / 127.f);

    uint16_t* cand = (uint16_t*)(smem + OFF_CAND);
    int*      cnt  = (int*)(smem + OFF_CNT);
    cnt[t] = 0;

    int acc[2][8][4];
#pragma unroll
    for (int mt = 0; mt < 2; mt++)
#pragma unroll
        for (int nt = 0; nt < 8; nt++)
#pragma unroll
            for (int j = 0; j < 4; j++) acc[mt][nt][j] = 0;
    float run[4] = {3.4e38f, 3.4e38f, 3.4e38f, 3.4e38f};

    load_stage(sb + OFF_A0, sb + OFF_B0, 0, r0, t);
    CP_ASYNC_COMMIT();
    __syncthreads();

    // per-lane ldmatrix address components
    const uint32_t a_row = (lane & 7) + ((lane >> 3) & 1) * 8;   // row within 16
    const uint32_t a_koff = ((lane >> 4) & 1) * 16;
    const uint32_t b_row = (lane & 7) + ((lane >> 4) & 1) * 8;   // code within 16
    const uint32_t b_koff = ((lane >> 3) & 1) * 16;

    for (int it = 0; it < TOTAL_IT; it++) {
        if (it + 1 < TOTAL_IT) {
            const uint32_t sa = sb + (((it + 1) & 1) ? OFF_A1 : OFF_A0);
            const uint32_t sB = sb + (((it + 1) & 1) ? OFF_B1 : OFF_B0);
            load_stage(sa, sB, it + 1, r0, t);
            CP_ASYNC_COMMIT();
            CP_ASYNC_WAIT1();
        } else {
            CP_ASYNC_WAIT0();
        }
        __syncthreads();

        {
            const uint32_t sa = sb + ((it & 1) ? OFF_A1 : OFF_A0);
            const uint32_t sB = sb + ((it & 1) ? OFF_B1 : OFF_B0);
#pragma unroll
            for (int kb = 0; kb < 4; kb++) {
                const uint32_t koff = kb * 32;
                uint32_t a[2][4];
#pragma unroll
                for (int mt = 0; mt < 2; mt++)
                    LDSM_X4(a[mt][0], a[mt][1], a[mt][2], a[mt][3],
                            sa + (warp_m * 32 + mt * 16 + a_row) * 144 + koff + a_koff);
#pragma unroll
                for (int ntp = 0; ntp < 4; ntp++) {
                    uint32_t b0, b1, b2, b3;
                    LDSM_X4(b0, b1, b2, b3,
                            sB + (warp_n * 64 + ntp * 16 + b_row) * 144 + koff + b_koff);
#pragma unroll
                    for (int mt = 0; mt < 2; mt++) {
                        MMA_S8(acc[mt][2 * ntp],     a[mt][0], a[mt][1], a[mt][2], a[mt][3], b0, b1);
                        MMA_S8(acc[mt][2 * ntp + 1], a[mt][0], a[mt][1], a[mt][2], a[mt][3], b2, b3);
                    }
                }
            }
        }

        // ---- tile boundary (every 4 stages = full K): scores + candidates ----
        if ((it & 3) == 3) {
            const int c0t = (it >> 2) * BC;
            float w2v[8][2];
#pragma unroll
            for (int nt = 0; nt < 8; nt++) {
                int c = c0t + warp_n * 64 + nt * 8 + 2 * c4;
                w2v[nt][0] = __ldg(&g_w2[c]);
                w2v[nt][1] = __ldg(&g_w2[c + 1]);
            }
#pragma unroll
            for (int rr = 0; rr < 4; rr++) {
                const int mt = rr >> 1, h = rr & 1;
                float s[16];
#pragma unroll
                for (int nt = 0; nt < 8; nt++) {
                    s[2 * nt]     = fmaf(s2, (float)acc[mt][nt][2 * h],     w2v[nt][0]);
                    s[2 * nt + 1] = fmaf(s2, (float)acc[mt][nt][2 * h + 1], w2v[nt][1]);
                }
                float m = s[0];
#pragma unroll
                for (int j = 1; j < 16; j++) m = fminf(m, s[j]);
                m = fminf(m, __shfl_xor_sync(0xffffffffu, m, 1));
                m = fminf(m, __shfl_xor_sync(0xffffffffu, m, 2));
                run[rr] = fminf(run[rr], m);
                const float thr = run[rr] + MARGIN;
                const int rowl = warp_m * 32 + mt * 16 + h * 8 + q;
#pragma unroll
                for (int nt = 0; nt < 8; nt++) {
#pragma unroll
                    for (int j = 0; j < 2; j++) {
                        if (s[2 * nt + j] <= thr) {
                            int pos = atomicAdd(&cnt[rowl * 2 + warp_n], 1);
                            if (pos < CAP)
                                cand[(rowl * 2 + warp_n) * CAP + pos] =
                                    (uint16_t)(c0t + warp_n * 64 + nt * 8 + 2 * c4 + j);
                        }
                    }
                }
            }
#pragma unroll
            for (int mt = 0; mt < 2; mt++)
#pragma unroll
                for (int nt = 0; nt < 8; nt++)
#pragma unroll
                    for (int j = 0; j < 4; j++) acc[mt][nt][j] = 0;
        }
        __syncthreads();
    }

    // ---- exact fp32 rescore (one warp per 16 rows) ----
    for (int j = 0; j < 16; j++) {
        const int rowl = wid * 16 + j;
        const int grow = r0 + rowl;
        float zreg[16];
#pragma unroll
        for (int p = 0; p < 16; p++) {
            int k = lane + 32 * p;
            zreg[p] = (k < DHALF) ? zr[(size_t)grow * DHALF + k]
                                  : zi[(size_t)grow * DHALF + k - DHALF];
        }
        int n0 = min(cnt[rowl * 2], CAP);
        int n1 = min(cnt[rowl * 2 + 1], CAP);
        float bv = 3.4e38f;
        int   bi = 0x7fffffff;
        for (int tt = 0; tt < n0 + n1; tt++) {
            int code = (tt < n0) ? cand[(rowl * 2) * CAP + tt]
                                 : cand[(rowl * 2 + 1) * CAP + tt - n0];
            const float* wrow = &w[(size_t)code * KDIM];
            float dot = 0.f;
#pragma unroll
            for (int p = 0; p < 16; p++) dot = fmaf(zreg[p], wrow[lane + 32 * p], dot);
#pragma unroll
            for (int m = 16; m >= 1; m >>= 1) dot += __shfl_xor_sync(0xffffffffu, dot, m);
            float ex = fmaf(-2.f, dot, __ldg(&g_w2[code]));
            if (ex < bv || (ex == bv && code < bi)) { bv = ex; bi = code; }
        }
        if (lane == 0) g_idx[grow] = bi;
    }
}

// ---------------------------------------------------------------------------
// Gather z_q, outputs, per-row loss, histogram
// out layout: [z_q_real N*D][z_q_imag N*D][loss N][idx N][entropy 1]
// ---------------------------------------------------------------------------
__global__ void gather_kernel(const float* __restrict__ zr, const float* __restrict__ zi,
                              const float* __restrict__ w, float* __restrict__ out) {
    int row  = blockIdx.x * 8 + (threadIdx.x >> 5);
    int lane = threadIdx.x & 31;
    if (row >= N_ROWS) return;

    int ci = g_idx[row];
    const float* wrow = w + (size_t)ci * KDIM;
    float ss = 0.f;
#pragma unroll
    for (int p = 0; p < DHALF / 32; p++) {
        int d = lane + p * 32;
        float wv = wrow[d];
        float zv = zr[(size_t)row * DHALF + d];
        out[(size_t)row * DHALF + d] = wv;
        float df = wv - zv;
        ss = fmaf(df, df, ss);
    }
#pragma unroll
    for (int p = 0; p < DHALF / 32; p++) {
        int d = lane + p * 32;
        float wv = wrow[DHALF + d];
        float zv = zi[(size_t)row * DHALF + d];
        out[(size_t)N_ROWS * DHALF + (size_t)row * DHALF + d] = wv;
        float df = wv - zv;
        ss = fmaf(df, df, ss);
    }
#pragma unroll
    for (int m = 16; m >= 1; m >>= 1) ss += __shfl_xor_sync(0xffffffffu, ss, m);
    if (lane == 0) {
        size_t base = (size_t)2 * N_ROWS * DHALF;
        out[base + row] = ss * (1.25f / (float)KDIM);
        out[base + N_ROWS + row] = (float)ci;
        atomicAdd(&g_counts[ci], 1);
    }
}

__global__ void entropy_kernel(float* __restrict__ out) {
    __shared__ float red[1024];
    int t = threadIdx.x;
    float s = 0.f;
    for (int v = t; v < VCODES; v += 1024) {
        float p = (float)g_counts[v] * (1.f / (float)N_ROWS);
        s += p * logf(p + 1e-10f);
    }
    red[t] = s;
    __syncthreads();
    for (int m = 512; m >= 1; m >>= 1) {
        if (t < m) red[t] += red[t + m];
        __syncthreads();
    }
    if (t == 0) out[(size_t)2 * N_ROWS * DHALF + 2 * N_ROWS] = -red[0];
}

// ---------------------------------------------------------------------------
extern "C" void kernel_launch(void* const* d_in, const int* in_sizes, int n_in,
                              void* d_out, int out_size) {
    const float* zr = (const float*)d_in[0];
    const float* zi = (const float*)d_in[1];
    const float* w  = (const float*)d_in[2];
    float* out = (float*)d_out;

    cudaFuncSetAttribute(vq_mma_kernel,
                         cudaFuncAttributeMaxDynamicSharedMemorySize, SMEM_TOTAL);

    init_kernel<<<(VCODES + 255) / 256, 256>>>();
    int* pmaxz; cudaGetSymbolAddress((void**)&pmaxz, g_maxz);
    int* pmaxw; cudaGetSymbolAddress((void**)&pmaxw, g_maxw);
    maxabs_kernel<<<256, 256>>>(zr, N_ROWS * DHALF / 4, pmaxz);
    maxabs_kernel<<<256, 256>>>(zi, N_ROWS * DHALF / 4, pmaxz);
    maxabs_kernel<<<256, 256>>>(w, VCODES * KDIM / 4, pmaxw);
    quant_z_kernel<<<(N_ROWS * KDIM / 4 + 255) / 256, 256>>>(zr, zi);
    quant_w_kernel<<<(VCODES * KDIM / 4 + 255) / 256, 256>>>(w);
    w2_kernel<<<VCODES / 8, 256>>>(w);
    vq_mma_kernel<<<N_ROWS / BR, NTHREADS, SMEM_TOTAL>>>(zr, zi, w);
    gather_kernel<<<N_ROWS / 8, 256>>>(zr, zi, w, out);
    entropy_kernel<<<1, 1024>>>(out);
}